// round 2
// baseline (speedup 1.0000x reference)
#include <cuda_runtime.h>
#include <cstdint>
#include <math.h>

#define BATCH 8
#define CH 256
#define MSP 16384          // H*W
#define KSPLIT 8
#define KC (MSP / KSPLIT)  // 2048
#define MAT (CH * CH)      // 65536

// ---------------- device scratch (no allocations allowed) ----------------
__device__ float g_part[KSPLIT * BATCH * MAT];  // 16 MB gram partials
__device__ float g_cov[BATCH * MAT];
__device__ float g_mu[BATCH * CH];
__device__ float g_invN[BATCH];
__device__ float g_rs[BATCH];
__device__ float g_bufY[2][BATCH * MAT];
__device__ float g_bufZ[2][BATCH * MAT];
__device__ float g_T[BATCH * MAT];
__device__ float g_yv[BATCH * CH];
__device__ float g_gate[BATCH * CH];

// ---------------- helpers ----------------
__device__ __forceinline__ float blockReduceSum256(float v) {
    __shared__ float sh[8];
    int lane = threadIdx.x & 31, w = threadIdx.x >> 5;
#pragma unroll
    for (int o = 16; o; o >>= 1) v += __shfl_down_sync(0xffffffffu, v, o);
    if (lane == 0) sh[w] = v;
    __syncthreads();
    if (threadIdx.x < 32) {
        v = (threadIdx.x < 8) ? sh[threadIdx.x] : 0.f;
#pragma unroll
        for (int o = 4; o; o >>= 1) v += __shfl_down_sync(0xffffffffu, v, o);
    }
    return v;  // valid in thread 0
}

// ---------------- per-(b,c) spatial mean ----------------
__global__ void __launch_bounds__(256) mean_kernel(const float* __restrict__ x) {
    int bc = blockIdx.x;  // 0..2047
    const float4* p = (const float4*)(x + (size_t)bc * MSP);
    float s = 0.f;
    for (int t = threadIdx.x; t < MSP / 4; t += 256) {
        float4 v = p[t];
        s += v.x + v.y + v.z + v.w;
    }
    s = blockReduceSum256(s);
    if (threadIdx.x == 0) g_mu[bc] = s * (1.f / MSP);
}

// ---------------- Gram partials: S = X X^T (upper 128-tiles only) ----------------
// grid (3, KSPLIT, BATCH); tile 0:(0,0) 1:(0,1) 2:(1,1); block 256 thr, 8x8 micro
__global__ void __launch_bounds__(256, 2) gram_kernel(const float* __restrict__ x) {
    int tile = blockIdx.x;
    int ks = blockIdx.y;
    int b = blockIdx.z;
    int ti = (tile == 2) ? 1 : 0;
    int tj = (tile == 0) ? 0 : 1;

    const float* Xa = x + ((size_t)b * CH + (size_t)ti * 128) * MSP + (size_t)ks * KC;
    const float* Xb = x + ((size_t)b * CH + (size_t)tj * 128) * MSP + (size_t)ks * KC;

    __shared__ float sA[32][132];  // [k][row], transposed
    __shared__ float sB[32][132];

    int tid = threadIdx.x;
    int f = tid & 7;    // which float4 along k (8 * 4 = 32)
    int r0 = tid >> 3;  // 0..31
    int tr = tid >> 4;  // 0..15
    int tc = tid & 15;  // 0..15

    float acc[8][8];
#pragma unroll
    for (int i = 0; i < 8; i++)
#pragma unroll
        for (int j = 0; j < 8; j++) acc[i][j] = 0.f;

    for (int kk = 0; kk < KC; kk += 32) {
#pragma unroll
        for (int rr = 0; rr < 4; rr++) {
            int r = r0 + rr * 32;
            float4 va = *(const float4*)(Xa + (size_t)r * MSP + kk + f * 4);
            float4 vb = *(const float4*)(Xb + (size_t)r * MSP + kk + f * 4);
            sA[f * 4 + 0][r] = va.x; sA[f * 4 + 1][r] = va.y;
            sA[f * 4 + 2][r] = va.z; sA[f * 4 + 3][r] = va.w;
            sB[f * 4 + 0][r] = vb.x; sB[f * 4 + 1][r] = vb.y;
            sB[f * 4 + 2][r] = vb.z; sB[f * 4 + 3][r] = vb.w;
        }
        __syncthreads();
#pragma unroll 8
        for (int k = 0; k < 32; k++) {
            float4 a0 = *(const float4*)&sA[k][tr * 4];
            float4 a1 = *(const float4*)&sA[k][64 + tr * 4];
            float4 b0 = *(const float4*)&sB[k][tc * 4];
            float4 b1 = *(const float4*)&sB[k][64 + tc * 4];
            float ar[8] = {a0.x, a0.y, a0.z, a0.w, a1.x, a1.y, a1.z, a1.w};
            float br[8] = {b0.x, b0.y, b0.z, b0.w, b1.x, b1.y, b1.z, b1.w};
#pragma unroll
            for (int i = 0; i < 8; i++)
#pragma unroll
                for (int j = 0; j < 8; j++)
                    acc[i][j] = fmaf(ar[i], br[j], acc[i][j]);
        }
        __syncthreads();
    }

    float* out = g_part + (size_t)(ks * BATCH + b) * MAT;
#pragma unroll
    for (int ii = 0; ii < 8; ii++) {
        int row = ti * 128 + ((ii < 4) ? (tr * 4 + ii) : (64 + tr * 4 + ii - 4));
        float4 v0 = make_float4(acc[ii][0], acc[ii][1], acc[ii][2], acc[ii][3]);
        float4 v1 = make_float4(acc[ii][4], acc[ii][5], acc[ii][6], acc[ii][7]);
        *(float4*)(out + (size_t)row * CH + tj * 128 + tc * 4) = v0;
        *(float4*)(out + (size_t)row * CH + tj * 128 + 64 + tc * 4) = v1;
    }
}

// ---------------- reduce K-split partials -> centered covariance ----------------
__global__ void __launch_bounds__(256) cov_reduce_kernel() {
    int b = blockIdx.y;
    int idx = blockIdx.x * 256 + threadIdx.x;  // i*256 + j
    int i = idx >> 8, j = idx & 255;
    int si = (i <= j) ? i : j;
    int sj = (i <= j) ? j : i;  // mirror from computed upper triangle
    float s = 0.f;
#pragma unroll
    for (int ks = 0; ks < KSPLIT; ks++)
        s += g_part[(size_t)(ks * BATCH + b) * MAT + (size_t)si * CH + sj];
    g_cov[(size_t)b * MAT + idx] =
        s * (1.f / MSP) - g_mu[b * CH + i] * g_mu[b * CH + j];
}

// ---------------- Frobenius norm per batch ----------------
__global__ void __launch_bounds__(256) frob_kernel() {
    int b = blockIdx.x;
    float s = 0.f;
    for (int t = threadIdx.x; t < MAT; t += 256) {
        float v = g_cov[(size_t)b * MAT + t];
        s += v * v;
    }
    s = blockReduceSum256(s);
    if (threadIdx.x == 0) {
        float n = sqrtf(s);
        g_invN[b] = 1.f / n;
        g_rs[b] = rsqrtf(n);
    }
}

// ---------------- init Y = cov/normA, Z = I ----------------
__global__ void __launch_bounds__(256) init_kernel() {
    int b = blockIdx.y;
    int idx = blockIdx.x * 256 + threadIdx.x;
    float inv = g_invN[b];
    g_bufY[0][(size_t)b * MAT + idx] = g_cov[(size_t)b * MAT + idx] * inv;
    int i = idx >> 8, j = idx & 255;
    g_bufZ[0][(size_t)b * MAT + idx] = (i == j) ? 1.f : 0.f;
}

// ---------------- batched 256x256x256 matmul body (64x64 tile, 4x4 micro) ----------------
__device__ __forceinline__ void mm256_body(const float* __restrict__ Am,
                                           const float* __restrict__ Bm,
                                           float* __restrict__ Cm, bool tEpi) {
    int bb = blockIdx.y;
    Am += (size_t)bb * MAT;
    Bm += (size_t)bb * MAT;
    Cm += (size_t)bb * MAT;
    int ti = blockIdx.x >> 2, tj = blockIdx.x & 3;

    __shared__ float sA[16][68];  // [k][row] (transposed)
    __shared__ float sB[16][68];  // [k][col]

    int tid = threadIdx.x;
    int tr = tid >> 4, tc = tid & 15;
    int la_k4 = tid & 3, la_r = tid >> 2;   // A loader: 64 rows x 4 float4
    int lb_j4 = tid & 15, lb_k = tid >> 4;  // B loader: 16 rows x 16 float4

    float acc[4][4] = {};

    for (int kk = 0; kk < CH; kk += 16) {
        float4 va = *(const float4*)(Am + (size_t)(ti * 64 + la_r) * CH + kk + la_k4 * 4);
        sA[la_k4 * 4 + 0][la_r] = va.x;
        sA[la_k4 * 4 + 1][la_r] = va.y;
        sA[la_k4 * 4 + 2][la_r] = va.z;
        sA[la_k4 * 4 + 3][la_r] = va.w;
        *(float4*)&sB[lb_k][lb_j4 * 4] =
            *(const float4*)(Bm + (size_t)(kk + lb_k) * CH + tj * 64 + lb_j4 * 4);
        __syncthreads();
#pragma unroll
        for (int k = 0; k < 16; k++) {
            float4 a4 = *(const float4*)&sA[k][tr * 4];
            float4 b4 = *(const float4*)&sB[k][tc * 4];
            float ar[4] = {a4.x, a4.y, a4.z, a4.w};
            float br[4] = {b4.x, b4.y, b4.z, b4.w};
#pragma unroll
            for (int i = 0; i < 4; i++)
#pragma unroll
                for (int j = 0; j < 4; j++)
                    acc[i][j] = fmaf(ar[i], br[j], acc[i][j]);
        }
        __syncthreads();
    }
#pragma unroll
    for (int i = 0; i < 4; i++) {
        int row = ti * 64 + tr * 4 + i;
#pragma unroll
        for (int j = 0; j < 4; j++) {
            int col = tj * 64 + tc * 4 + j;
            float v = acc[i][j];
            if (tEpi) v = ((row == col) ? 1.5f : 0.f) - 0.5f * v;
            Cm[(size_t)row * CH + col] = v;
        }
    }
}

// T = 1.5 I - 0.5 * (Z @ Y)
__global__ void __launch_bounds__(256) mmT_kernel(int cur) {
    mm256_body(g_bufZ[cur], g_bufY[cur], g_T, true);
}

// z==0: Ynew = Y @ T ; z==1: Znew = T @ Z
__global__ void __launch_bounds__(256) mmYZ_kernel(int cur) {
    const float* A = (blockIdx.z == 0) ? g_bufY[cur] : g_T;
    const float* B = (blockIdx.z == 0) ? g_T : g_bufZ[cur];
    float* C = (blockIdx.z == 0) ? g_bufY[cur ^ 1] : g_bufZ[cur ^ 1];
    mm256_body(A, B, C, false);
}

// ---------------- y = rowmean(Z)/sqrt(normA) ----------------
__global__ void __launch_bounds__(256) rowmean_kernel(int cur) {
    int b = blockIdx.x, c = threadIdx.x;
    const float4* row = (const float4*)(g_bufZ[cur] + ((size_t)b * CH + c) * CH);
    float s = 0.f;
#pragma unroll 8
    for (int d = 0; d < CH / 4; d++) {
        float4 v = row[d];
        s += v.x + v.y + v.z + v.w;
    }
    g_yv[b * CH + c] = s * (1.f / CH) * g_rs[b];
}

// ---------------- squeeze-excite MLP + sigmoid ----------------
__global__ void __launch_bounds__(256) se_kernel(const float* __restrict__ w1,
                                                 const float* __restrict__ b1,
                                                 const float* __restrict__ w2,
                                                 const float* __restrict__ b2) {
    int b = blockIdx.x;
    int tid = threadIdx.x;
    __shared__ float ys[CH];
    __shared__ float hs[32];
    ys[tid] = g_yv[b * CH + tid];
    __syncthreads();
    if (tid < 32) {
        float s = b1[tid];
        const float* w = w1 + tid * CH;
#pragma unroll 8
        for (int c = 0; c < CH; c++) s = fmaf(ys[c], w[c], s);
        hs[tid] = fmaxf(s, 0.f);
    }
    __syncthreads();
    float s = b2[tid];
    const float* w = w2 + tid * 32;
#pragma unroll
    for (int j = 0; j < 32; j++) s = fmaf(hs[j], w[j], s);
    g_gate[b * CH + tid] = 1.f / (1.f + expf(-s));
}

// ---------------- out = x * gate[b,c] ----------------
__global__ void __launch_bounds__(256) scale_kernel(const float* __restrict__ x,
                                                    float* __restrict__ out) {
    const float4* xi = (const float4*)x;
    float4* oo = (float4*)out;
    const size_t total = (size_t)BATCH * CH * MSP / 4;
    for (size_t i = (size_t)blockIdx.x * blockDim.x + threadIdx.x; i < total;
         i += (size_t)gridDim.x * blockDim.x) {
        float g = g_gate[i >> 12];  // (i*4) / 16384 -> b*256+c
        float4 v = xi[i];
        v.x *= g; v.y *= g; v.z *= g; v.w *= g;
        oo[i] = v;
    }
}

// ---------------- launch ----------------
extern "C" void kernel_launch(void* const* d_in, const int* in_sizes, int n_in,
                              void* d_out, int out_size) {
    const float* x = (const float*)d_in[0];
    const float* w1 = (const float*)d_in[1];
    const float* b1 = (const float*)d_in[2];
    const float* w2 = (const float*)d_in[3];
    const float* b2 = (const float*)d_in[4];
    float* out = (float*)d_out;

    mean_kernel<<<BATCH * CH, 256>>>(x);
    gram_kernel<<<dim3(3, KSPLIT, BATCH), 256>>>(x);
    cov_reduce_kernel<<<dim3(MAT / 256, BATCH), 256>>>();
    frob_kernel<<<BATCH, 256>>>();
    init_kernel<<<dim3(MAT / 256, BATCH), 256>>>();

    int cur = 0;
    for (int it = 0; it < 5; it++) {
        mmT_kernel<<<dim3(16, BATCH), 256>>>(cur);
        mmYZ_kernel<<<dim3(16, BATCH, 2), 256>>>(cur);
        cur ^= 1;
    }

    rowmean_kernel<<<BATCH, 256>>>(cur);
    se_kernel<<<BATCH, 256>>>(w1, b1, w2, b2);
    scale_kernel<<<8192, 256>>>(x, out);
}

// round 5
// speedup vs baseline: 1.5407x; 1.5407x over previous
#include <cuda_runtime.h>
#include <cuda_bf16.h>
#include <cstdint>
#include <math.h>

#define BATCH 8
#define CH 256
#define MSP 16384          // H*W
#define MAT (CH * CH)      // 65536
#define KSG 4              // gram K-split
#define KLOC (MSP / KSG)   // 4096
#define KCH 32             // k per pipeline chunk
#define NCH (KLOC / KCH)   // 128
#define ASTR 40            // smem row stride in bf16 (80 B): conflict-free for ldmatrix

// ---------------- device scratch (no allocations allowed) ----------------
__device__ __nv_bfloat16 g_hi[(size_t)BATCH * CH * MSP];
__device__ __nv_bfloat16 g_lo[(size_t)BATCH * CH * MSP];
__device__ float g_g1p[KSG][BATCH * MAT];
__device__ float g_g2p[KSG][BATCH * MAT];
__device__ float g_cov[BATCH * MAT];
__device__ float g_mu[BATCH * CH];
__device__ float g_fpart[BATCH][256];
__device__ float g_invN[BATCH];
__device__ float g_rs[BATCH];
__device__ float g_bufY[2][BATCH * MAT];
__device__ float g_bufZ[2][BATCH * MAT];
__device__ float g_T[BATCH * MAT];
__device__ float g_yv[BATCH * CH];
__device__ float g_gate[BATCH * CH];

// ---------------- PTX helpers (baseline ISA only — no 'a'-target features) ----
__device__ __forceinline__ uint32_t smem_u32(const void* p) {
    uint32_t a;
    asm("{ .reg .u64 t; cvta.to.shared.u64 t, %1; cvt.u32.u64 %0, t; }"
        : "=r"(a) : "l"(p));
    return a;
}
#define CP_ASYNC16(dst, src) \
    asm volatile("cp.async.cg.shared.global [%0], [%1], 16;" :: "r"(dst), "l"(src))
#define CP_COMMIT() asm volatile("cp.async.commit_group;" ::: "memory")
#define CP_WAIT1() asm volatile("cp.async.wait_group 1;" ::: "memory")

__device__ __forceinline__ void ldm_x4(uint32_t* r, uint32_t addr) {
    asm volatile("ldmatrix.sync.aligned.m8n8.x4.shared.b16 {%0,%1,%2,%3}, [%4];"
                 : "=r"(r[0]), "=r"(r[1]), "=r"(r[2]), "=r"(r[3]) : "r"(addr));
}
__device__ __forceinline__ void ldm_x2(uint32_t* r, uint32_t addr) {
    asm volatile("ldmatrix.sync.aligned.m8n8.x2.shared.b16 {%0,%1}, [%2];"
                 : "=r"(r[0]), "=r"(r[1]) : "r"(addr));
}
__device__ __forceinline__ void mma_bf16(float* c, const uint32_t* a, const uint32_t* b) {
    asm volatile(
        "mma.sync.aligned.m16n8k16.row.col.f32.bf16.bf16.f32 "
        "{%0,%1,%2,%3}, {%4,%5,%6,%7}, {%8,%9}, {%0,%1,%2,%3};"
        : "+f"(c[0]), "+f"(c[1]), "+f"(c[2]), "+f"(c[3])
        : "r"(a[0]), "r"(a[1]), "r"(a[2]), "r"(a[3]), "r"(b[0]), "r"(b[1]));
}

// ---------------- helpers ----------------
__device__ __forceinline__ float blockReduceSum256(float v) {
    __shared__ float sh[8];
    int lane = threadIdx.x & 31, w = threadIdx.x >> 5;
#pragma unroll
    for (int o = 16; o; o >>= 1) v += __shfl_down_sync(0xffffffffu, v, o);
    if (lane == 0) sh[w] = v;
    __syncthreads();
    if (threadIdx.x < 32) {
        v = (threadIdx.x < 8) ? sh[threadIdx.x] : 0.f;
#pragma unroll
        for (int o = 4; o; o >>= 1) v += __shfl_down_sync(0xffffffffu, v, o);
    }
    return v;  // valid in thread 0
}

// ---------------- fused: bf16 hi/lo split + per-(b,c) spatial mean ----------------
__global__ void __launch_bounds__(256) convert_kernel(const float* __restrict__ x) {
    int bc = blockIdx.x;  // 0..2047
    const float4* p = (const float4*)(x + (size_t)bc * MSP);
    __nv_bfloat162* hi2 = (__nv_bfloat162*)g_hi + (size_t)bc * (MSP / 2);
    __nv_bfloat162* lo2 = (__nv_bfloat162*)g_lo + (size_t)bc * (MSP / 2);
    float s = 0.f;
    for (int t = threadIdx.x; t < MSP / 4; t += 256) {
        float4 v = p[t];
        s += v.x + v.y + v.z + v.w;
        __nv_bfloat16 h0 = __float2bfloat16(v.x);
        __nv_bfloat16 h1 = __float2bfloat16(v.y);
        __nv_bfloat16 h2 = __float2bfloat16(v.z);
        __nv_bfloat16 h3 = __float2bfloat16(v.w);
        __nv_bfloat16 l0 = __float2bfloat16(v.x - __bfloat162float(h0));
        __nv_bfloat16 l1 = __float2bfloat16(v.y - __bfloat162float(h1));
        __nv_bfloat16 l2 = __float2bfloat16(v.z - __bfloat162float(h2));
        __nv_bfloat16 l3 = __float2bfloat16(v.w - __bfloat162float(h3));
        __nv_bfloat162 a, b, c, d;
        a.x = h0; a.y = h1; b.x = h2; b.y = h3;
        c.x = l0; c.y = l1; d.x = l2; d.y = l3;
        hi2[t * 2] = a; hi2[t * 2 + 1] = b;
        lo2[t * 2] = c; lo2[t * 2 + 1] = d;
    }
    s = blockReduceSum256(s);
    if (threadIdx.x == 0) g_mu[bc] = s * (1.f / MSP);
}

// ---------------- Gram via HMMA (mma.sync bf16) ----------------
// grid (7 tile-pairs, KSG, BATCH). pair 0..2: G1=hi.hi^T tiles (0,0),(0,1),(1,1)
//                                  pair 3..6: G2=hi.lo^T tiles (0,0),(0,1),(1,0),(1,1)
// 256 threads = 8 warps (2x4), warp tile 64x32, k-chunk 32, cp.async double buffer.
__global__ void __launch_bounds__(256, 2) gram_hmma_kernel() {
    __shared__ __nv_bfloat16 sA[2][128 * ASTR];
    __shared__ __nv_bfloat16 sB[2][128 * ASTR];

    int tid = threadIdx.x, wid = tid >> 5, lane = tid & 31;
    int pair = blockIdx.x, ks = blockIdx.y, b = blockIdx.z;
    int mat = (pair >= 3);
    int t = mat ? (pair - 3) : pair;
    int ti, tj;
    if (mat) { ti = t >> 1; tj = t & 1; }
    else     { ti = (t == 2) ? 1 : 0; tj = (t == 0) ? 0 : 1; }

    const __nv_bfloat16* Ag =
        g_hi + ((size_t)b * CH + (size_t)ti * 128) * MSP + (size_t)ks * KLOC;
    const __nv_bfloat16* Bg =
        (mat ? g_lo : g_hi) + ((size_t)b * CH + (size_t)tj * 128) * MSP + (size_t)ks * KLOC;

    uint32_t sA0 = smem_u32(&sA[0][0]);
    uint32_t sB0 = smem_u32(&sB[0][0]);
    const uint32_t stageA = 128 * ASTR * 2;  // bytes per stage
    const uint32_t stageB = 128 * ASTR * 2;

    // loader: thread -> row = tid>>1, two 16B segments starting at (tid&1)*2
    int lr = tid >> 1;
    int lf = (tid & 1) * 2;
    uint32_t dstA = sA0 + (uint32_t)(lr * ASTR + lf * 8) * 2;
    uint32_t dstB = sB0 + (uint32_t)(lr * ASTR + lf * 8) * 2;

    int warp_m = wid >> 2, warp_n = wid & 3;
    // ldmatrix element offsets (within a stage), in bytes
    uint32_t a_off[4], b_off[4];
#pragma unroll
    for (int mt = 0; mt < 4; mt++) {
        int row = warp_m * 64 + mt * 16 + (lane & 15);
        a_off[mt] = (uint32_t)(row * ASTR + (lane >> 4) * 8) * 2;
    }
#pragma unroll
    for (int nt = 0; nt < 4; nt++) {
        int l2 = lane & 15;
        int row = warp_n * 32 + nt * 8 + (l2 & 7);
        b_off[nt] = (uint32_t)(row * ASTR + (l2 >> 3) * 8) * 2;
    }

    float acc[4][4][4];
#pragma unroll
    for (int i = 0; i < 4; i++)
#pragma unroll
        for (int j = 0; j < 4; j++)
#pragma unroll
            for (int k = 0; k < 4; k++) acc[i][j][k] = 0.f;

    // prologue: chunk 0 -> stage 0
    {
        const __nv_bfloat16* Ap = Ag + (size_t)lr * MSP + lf * 8;
        const __nv_bfloat16* Bp = Bg + (size_t)lr * MSP + lf * 8;
        CP_ASYNC16(dstA, Ap); CP_ASYNC16(dstA + 16, Ap + 8);
        CP_ASYNC16(dstB, Bp); CP_ASYNC16(dstB + 16, Bp + 8);
        CP_COMMIT();
    }

    for (int c = 0; c < NCH; c++) {
        int s = c & 1;
        if (c + 1 < NCH) {
            int sn = (c + 1) & 1;
            const __nv_bfloat16* Ap = Ag + (size_t)lr * MSP + (c + 1) * KCH + lf * 8;
            const __nv_bfloat16* Bp = Bg + (size_t)lr * MSP + (c + 1) * KCH + lf * 8;
            CP_ASYNC16(dstA + sn * stageA, Ap); CP_ASYNC16(dstA + sn * stageA + 16, Ap + 8);
            CP_ASYNC16(dstB + sn * stageB, Bp); CP_ASYNC16(dstB + sn * stageB + 16, Bp + 8);
        }
        CP_COMMIT();
        CP_WAIT1();
        __syncthreads();

        uint32_t baseA = sA0 + s * stageA;
        uint32_t baseB = sB0 + s * stageB;
#pragma unroll
        for (int kh = 0; kh < 2; kh++) {
            uint32_t af[4][4], bf[4][2];
#pragma unroll
            for (int mt = 0; mt < 4; mt++) ldm_x4(af[mt], baseA + a_off[mt] + kh * 32);
#pragma unroll
            for (int nt = 0; nt < 4; nt++) ldm_x2(bf[nt], baseB + b_off[nt] + kh * 32);
#pragma unroll
            for (int mt = 0; mt < 4; mt++)
#pragma unroll
                for (int nt = 0; nt < 4; nt++) mma_bf16(acc[mt][nt], af[mt], bf[nt]);
        }
        __syncthreads();
    }

    // epilogue: direct store of warp fragments
    float* dst = (mat ? g_g2p[ks] : g_g1p[ks]) + (size_t)b * MAT;
    int grp = lane >> 2, qp = lane & 3;
#pragma unroll
    for (int mt = 0; mt < 4; mt++) {
        int row0 = ti * 128 + warp_m * 64 + mt * 16;
#pragma unroll
        for (int nt = 0; nt < 4; nt++) {
            int col0 = tj * 128 + warp_n * 32 + nt * 8 + qp * 2;
            float2 v0 = make_float2(acc[mt][nt][0], acc[mt][nt][1]);
            float2 v1 = make_float2(acc[mt][nt][2], acc[mt][nt][3]);
            *(float2*)(dst + (size_t)(row0 + grp) * CH + col0) = v0;
            *(float2*)(dst + (size_t)(row0 + grp + 8) * CH + col0) = v1;
        }
    }
}

// ---------------- reduce partials -> centered covariance (+frobenius partials) ----
__global__ void __launch_bounds__(256) cov_reduce_kernel() {
    int b = blockIdx.y;
    int idx = blockIdx.x * 256 + threadIdx.x;  // i*256 + j
    int i = idx >> 8, j = idx & 255;
    int si = (i <= j) ? i : j;
    int sj = (i <= j) ? j : i;
    float s = 0.f;
#pragma unroll
    for (int ks = 0; ks < KSG; ks++) {
        s += g_g1p[ks][(size_t)b * MAT + si * CH + sj];      // G1 upper tiles only
        s += g_g2p[ks][(size_t)b * MAT + idx];               // G2 full
        s += g_g2p[ks][(size_t)b * MAT + j * CH + i];        // G2^T
    }
    float v = s * (1.f / MSP) - g_mu[b * CH + i] * g_mu[b * CH + j];
    g_cov[(size_t)b * MAT + idx] = v;
    float sq = blockReduceSum256(v * v);
    if (threadIdx.x == 0) g_fpart[b][blockIdx.x] = sq;
}

// ---------------- finalize frobenius norm ----------------
__global__ void __launch_bounds__(256) frob2_kernel() {
    int b = blockIdx.x;
    float s = blockReduceSum256(g_fpart[b][threadIdx.x]);
    if (threadIdx.x == 0) {
        float n = sqrtf(s);
        g_invN[b] = 1.f / n;
        g_rs[b] = rsqrtf(n);
    }
}

// ---------------- init Y = cov/normA, Z = I ----------------
__global__ void __launch_bounds__(256) init_kernel() {
    int b = blockIdx.y;
    int idx = blockIdx.x * 256 + threadIdx.x;
    float inv = g_invN[b];
    g_bufY[0][(size_t)b * MAT + idx] = g_cov[(size_t)b * MAT + idx] * inv;
    int i = idx >> 8, j = idx & 255;
    g_bufZ[0][(size_t)b * MAT + idx] = (i == j) ? 1.f : 0.f;
}

// ---------------- batched 256x256x256 matmul body (64x64 tile, 4x4 micro) ------
__device__ __forceinline__ void mm256_body(const float* __restrict__ Am,
                                           const float* __restrict__ Bm,
                                           float* __restrict__ Cm, bool tEpi) {
    int bb = blockIdx.y;
    Am += (size_t)bb * MAT;
    Bm += (size_t)bb * MAT;
    Cm += (size_t)bb * MAT;
    int ti = blockIdx.x >> 2, tj = blockIdx.x & 3;

    __shared__ float sA[16][68];
    __shared__ float sB[16][68];

    int tid = threadIdx.x;
    int tr = tid >> 4, tc = tid & 15;
    int la_k4 = tid & 3, la_r = tid >> 2;
    int lb_j4 = tid & 15, lb_k = tid >> 4;

    float acc[4][4] = {};

    for (int kk = 0; kk < CH; kk += 16) {
        float4 va = *(const float4*)(Am + (size_t)(ti * 64 + la_r) * CH + kk + la_k4 * 4);
        sA[la_k4 * 4 + 0][la_r] = va.x;
        sA[la_k4 * 4 + 1][la_r] = va.y;
        sA[la_k4 * 4 + 2][la_r] = va.z;
        sA[la_k4 * 4 + 3][la_r] = va.w;
        *(float4*)&sB[lb_k][lb_j4 * 4] =
            *(const float4*)(Bm + (size_t)(kk + lb_k) * CH + tj * 64 + lb_j4 * 4);
        __syncthreads();
#pragma unroll
        for (int k = 0; k < 16; k++) {
            float4 a4 = *(const float4*)&sA[k][tr * 4];
            float4 b4 = *(const float4*)&sB[k][tc * 4];
            float ar[4] = {a4.x, a4.y, a4.z, a4.w};
            float br[4] = {b4.x, b4.y, b4.z, b4.w};
#pragma unroll
            for (int i = 0; i < 4; i++)
#pragma unroll
                for (int j = 0; j < 4; j++)
                    acc[i][j] = fmaf(ar[i], br[j], acc[i][j]);
        }
        __syncthreads();
    }
#pragma unroll
    for (int i = 0; i < 4; i++) {
        int row = ti * 64 + tr * 4 + i;
#pragma unroll
        for (int j = 0; j < 4; j++) {
            int col = tj * 64 + tc * 4 + j;
            float v = acc[i][j];
            if (tEpi) v = ((row == col) ? 1.5f : 0.f) - 0.5f * v;
            Cm[(size_t)row * CH + col] = v;
        }
    }
}

__global__ void __launch_bounds__(256) mmT_kernel(int cur) {
    mm256_body(g_bufZ[cur], g_bufY[cur], g_T, true);
}
__global__ void __launch_bounds__(256) mmYZ_kernel(int cur) {
    const float* A = (blockIdx.z == 0) ? g_bufY[cur] : g_T;
    const float* B = (blockIdx.z == 0) ? g_T : g_bufZ[cur];
    float* C = (blockIdx.z == 0) ? g_bufY[cur ^ 1] : g_bufZ[cur ^ 1];
    mm256_body(A, B, C, false);
}

// ---------------- y = rowmean(Z)/sqrt(normA) ----------------
__global__ void __launch_bounds__(256) rowmean_kernel(int cur) {
    int b = blockIdx.x, c = threadIdx.x;
    const float4* row = (const float4*)(g_bufZ[cur] + ((size_t)b * CH + c) * CH);
    float s = 0.f;
#pragma unroll 8
    for (int d = 0; d < CH / 4; d++) {
        float4 v = row[d];
        s += v.x + v.y + v.z + v.w;
    }
    g_yv[b * CH + c] = s * (1.f / CH) * g_rs[b];
}

// ---------------- squeeze-excite MLP + sigmoid ----------------
__global__ void __launch_bounds__(256) se_kernel(const float* __restrict__ w1,
                                                 const float* __restrict__ b1,
                                                 const float* __restrict__ w2,
                                                 const float* __restrict__ b2) {
    int b = blockIdx.x;
    int tid = threadIdx.x;
    __shared__ float ys[CH];
    __shared__ float hs[32];
    ys[tid] = g_yv[b * CH + tid];
    __syncthreads();
    if (tid < 32) {
        float s = b1[tid];
        const float* w = w1 + tid * CH;
#pragma unroll 8
        for (int c = 0; c < CH; c++) s = fmaf(ys[c], w[c], s);
        hs[tid] = fmaxf(s, 0.f);
    }
    __syncthreads();
    float s = b2[tid];
    const float* w = w2 + tid * 32;
#pragma unroll
    for (int j = 0; j < 32; j++) s = fmaf(hs[j], w[j], s);
    g_gate[b * CH + tid] = 1.f / (1.f + expf(-s));
}

// ---------------- out = x * gate[b,c] ----------------
__global__ void __launch_bounds__(256) scale_kernel(const float* __restrict__ x,
                                                    float* __restrict__ out) {
    const float4* xi = (const float4*)x;
    float4* oo = (float4*)out;
    const size_t total = (size_t)BATCH * CH * MSP / 4;
    for (size_t i = (size_t)blockIdx.x * blockDim.x + threadIdx.x; i < total;
         i += (size_t)gridDim.x * blockDim.x) {
        float g = g_gate[i >> 12];
        float4 v = xi[i];
        v.x *= g; v.y *= g; v.z *= g; v.w *= g;
        oo[i] = v;
    }
}

// ---------------- launch ----------------
extern "C" void kernel_launch(void* const* d_in, const int* in_sizes, int n_in,
                              void* d_out, int out_size) {
    const float* x = (const float*)d_in[0];
    const float* w1 = (const float*)d_in[1];
    const float* b1 = (const float*)d_in[2];
    const float* w2 = (const float*)d_in[3];
    const float* b2 = (const float*)d_in[4];
    float* out = (float*)d_out;

    convert_kernel<<<BATCH * CH, 256>>>(x);
    gram_hmma_kernel<<<dim3(7, KSG, BATCH), 256>>>();
    cov_reduce_kernel<<<dim3(256, BATCH), 256>>>();
    frob2_kernel<<<BATCH, 256>>>();
    init_kernel<<<dim3(MAT / 256, BATCH), 256>>>();

    int cur = 0;
    for (int it = 0; it < 5; it++) {
        mmT_kernel<<<dim3(16, BATCH), 256>>>(cur);
        mmYZ_kernel<<<dim3(16, BATCH, 2), 256>>>(cur);
        cur ^= 1;
    }

    rowmean_kernel<<<BATCH, 256>>>(cur);
    se_kernel<<<BATCH, 256>>>(w1, b1, w2, b2);
    scale_kernel<<<8192, 256>>>(x, out);
}

// round 6
// speedup vs baseline: 1.8214x; 1.1822x over previous
#include <cuda_runtime.h>
#include <cuda_bf16.h>
#include <cstdint>
#include <math.h>

#define BATCH 8
#define CH 256
#define MSP 16384          // H*W
#define MAT (CH * CH)      // 65536
#define KSG 4              // gram K-split
#define KLOC (MSP / KSG)   // 4096
#define KCH 32             // gram k per pipeline chunk
#define NCH (KLOC / KCH)   // 128
#define ASTR 40            // gram smem row stride (bf16): conflict-free ldmatrix
#define NSTR 72            // NS smem row stride (bf16): 144B, conflict-free
#define NS_STAGE (64 * NSTR)

// ---------------- device scratch (no allocations allowed) ----------------
__device__ __nv_bfloat16 g_hi[(size_t)BATCH * CH * MSP];
__device__ __nv_bfloat16 g_lo[(size_t)BATCH * CH * MSP];
__device__ float g_g1p[KSG][BATCH * MAT];
__device__ float g_g2p[KSG][BATCH * MAT];
__device__ float g_cov[BATCH * MAT];
__device__ float g_mu[BATCH * CH];
__device__ float g_fpart[BATCH][256];
__device__ float g_invN[BATCH];
__device__ float g_rs[BATCH];
__device__ __nv_bfloat16 g_Yh[2][BATCH * MAT];
__device__ __nv_bfloat16 g_Yl[2][BATCH * MAT];
__device__ __nv_bfloat16 g_Zh[2][BATCH * MAT];
__device__ __nv_bfloat16 g_Zl[2][BATCH * MAT];
__device__ __nv_bfloat16 g_Th[BATCH * MAT];
__device__ __nv_bfloat16 g_Tl[BATCH * MAT];
__device__ float g_Zf[BATCH * MAT];
__device__ float g_yv[BATCH * CH];
__device__ float g_gate[BATCH * CH];

// ---------------- PTX helpers (baseline ISA only — no 'a'-target features) ----
__device__ __forceinline__ uint32_t smem_u32(const void* p) {
    uint32_t a;
    asm("{ .reg .u64 t; cvta.to.shared.u64 t, %1; cvt.u32.u64 %0, t; }"
        : "=r"(a) : "l"(p));
    return a;
}
#define CP_ASYNC16(dst, src) \
    asm volatile("cp.async.cg.shared.global [%0], [%1], 16;" :: "r"(dst), "l"(src))
#define CP_COMMIT() asm volatile("cp.async.commit_group;" ::: "memory")
#define CP_WAIT1() asm volatile("cp.async.wait_group 1;" ::: "memory")

__device__ __forceinline__ void ldm_x4(uint32_t* r, uint32_t addr) {
    asm volatile("ldmatrix.sync.aligned.m8n8.x4.shared.b16 {%0,%1,%2,%3}, [%4];"
                 : "=r"(r[0]), "=r"(r[1]), "=r"(r[2]), "=r"(r[3]) : "r"(addr));
}
__device__ __forceinline__ void ldm_x2(uint32_t* r, uint32_t addr) {
    asm volatile("ldmatrix.sync.aligned.m8n8.x2.shared.b16 {%0,%1}, [%2];"
                 : "=r"(r[0]), "=r"(r[1]) : "r"(addr));
}
__device__ __forceinline__ void mma_bf16(float* c, const uint32_t* a, const uint32_t* b) {
    asm volatile(
        "mma.sync.aligned.m16n8k16.row.col.f32.bf16.bf16.f32 "
        "{%0,%1,%2,%3}, {%4,%5,%6,%7}, {%8,%9}, {%0,%1,%2,%3};"
        : "+f"(c[0]), "+f"(c[1]), "+f"(c[2]), "+f"(c[3])
        : "r"(a[0]), "r"(a[1]), "r"(a[2]), "r"(a[3]), "r"(b[0]), "r"(b[1]));
}

// ---------------- helpers ----------------
__device__ __forceinline__ float blockReduceSum256(float v) {
    __shared__ float sh[8];
    int lane = threadIdx.x & 31, w = threadIdx.x >> 5;
#pragma unroll
    for (int o = 16; o; o >>= 1) v += __shfl_down_sync(0xffffffffu, v, o);
    if (lane == 0) sh[w] = v;
    __syncthreads();
    if (threadIdx.x < 32) {
        v = (threadIdx.x < 8) ? sh[threadIdx.x] : 0.f;
#pragma unroll
        for (int o = 4; o; o >>= 1) v += __shfl_down_sync(0xffffffffu, v, o);
    }
    return v;  // valid in thread 0
}

// ---------------- fused: bf16 hi/lo split + per-(b,c) spatial mean ----------------
__global__ void __launch_bounds__(256) convert_kernel(const float* __restrict__ x) {
    int bc = blockIdx.x;  // 0..2047
    const float4* p = (const float4*)(x + (size_t)bc * MSP);
    __nv_bfloat162* hi2 = (__nv_bfloat162*)g_hi + (size_t)bc * (MSP / 2);
    __nv_bfloat162* lo2 = (__nv_bfloat162*)g_lo + (size_t)bc * (MSP / 2);
    float s = 0.f;
    for (int t = threadIdx.x; t < MSP / 4; t += 256) {
        float4 v = p[t];
        s += v.x + v.y + v.z + v.w;
        __nv_bfloat16 h0 = __float2bfloat16(v.x);
        __nv_bfloat16 h1 = __float2bfloat16(v.y);
        __nv_bfloat16 h2 = __float2bfloat16(v.z);
        __nv_bfloat16 h3 = __float2bfloat16(v.w);
        __nv_bfloat16 l0 = __float2bfloat16(v.x - __bfloat162float(h0));
        __nv_bfloat16 l1 = __float2bfloat16(v.y - __bfloat162float(h1));
        __nv_bfloat16 l2 = __float2bfloat16(v.z - __bfloat162float(h2));
        __nv_bfloat16 l3 = __float2bfloat16(v.w - __bfloat162float(h3));
        __nv_bfloat162 a, b, c, d;
        a.x = h0; a.y = h1; b.x = h2; b.y = h3;
        c.x = l0; c.y = l1; d.x = l2; d.y = l3;
        hi2[t * 2] = a; hi2[t * 2 + 1] = b;
        lo2[t * 2] = c; lo2[t * 2 + 1] = d;
    }
    s = blockReduceSum256(s);
    if (threadIdx.x == 0) g_mu[bc] = s * (1.f / MSP);
}

// ---------------- Gram via HMMA (mma.sync bf16) ----------------
__global__ void __launch_bounds__(256, 2) gram_hmma_kernel() {
    __shared__ __nv_bfloat16 sA[2][128 * ASTR];
    __shared__ __nv_bfloat16 sB[2][128 * ASTR];

    int tid = threadIdx.x, wid = tid >> 5, lane = tid & 31;
    int pair = blockIdx.x, ks = blockIdx.y, b = blockIdx.z;
    int mat = (pair >= 3);
    int t = mat ? (pair - 3) : pair;
    int ti, tj;
    if (mat) { ti = t >> 1; tj = t & 1; }
    else     { ti = (t == 2) ? 1 : 0; tj = (t == 0) ? 0 : 1; }

    const __nv_bfloat16* Ag =
        g_hi + ((size_t)b * CH + (size_t)ti * 128) * MSP + (size_t)ks * KLOC;
    const __nv_bfloat16* Bg =
        (mat ? g_lo : g_hi) + ((size_t)b * CH + (size_t)tj * 128) * MSP + (size_t)ks * KLOC;

    uint32_t sA0 = smem_u32(&sA[0][0]);
    uint32_t sB0 = smem_u32(&sB[0][0]);
    const uint32_t stageA = 128 * ASTR * 2;
    const uint32_t stageB = 128 * ASTR * 2;

    int lr = tid >> 1;
    int lf = (tid & 1) * 2;
    uint32_t dstA = sA0 + (uint32_t)(lr * ASTR + lf * 8) * 2;
    uint32_t dstB = sB0 + (uint32_t)(lr * ASTR + lf * 8) * 2;

    int warp_m = wid >> 2, warp_n = wid & 3;
    uint32_t a_off[4], b_off[4];
#pragma unroll
    for (int mt = 0; mt < 4; mt++) {
        int row = warp_m * 64 + mt * 16 + (lane & 15);
        a_off[mt] = (uint32_t)(row * ASTR + (lane >> 4) * 8) * 2;
    }
#pragma unroll
    for (int nt = 0; nt < 4; nt++) {
        int l2 = lane & 15;
        int row = warp_n * 32 + nt * 8 + (l2 & 7);
        b_off[nt] = (uint32_t)(row * ASTR + (l2 >> 3) * 8) * 2;
    }

    float acc[4][4][4];
#pragma unroll
    for (int i = 0; i < 4; i++)
#pragma unroll
        for (int j = 0; j < 4; j++)
#pragma unroll
            for (int k = 0; k < 4; k++) acc[i][j][k] = 0.f;

    {
        const __nv_bfloat16* Ap = Ag + (size_t)lr * MSP + lf * 8;
        const __nv_bfloat16* Bp = Bg + (size_t)lr * MSP + lf * 8;
        CP_ASYNC16(dstA, Ap); CP_ASYNC16(dstA + 16, Ap + 8);
        CP_ASYNC16(dstB, Bp); CP_ASYNC16(dstB + 16, Bp + 8);
        CP_COMMIT();
    }

    for (int c = 0; c < NCH; c++) {
        int s = c & 1;
        if (c + 1 < NCH) {
            int sn = (c + 1) & 1;
            const __nv_bfloat16* Ap = Ag + (size_t)lr * MSP + (c + 1) * KCH + lf * 8;
            const __nv_bfloat16* Bp = Bg + (size_t)lr * MSP + (c + 1) * KCH + lf * 8;
            CP_ASYNC16(dstA + sn * stageA, Ap); CP_ASYNC16(dstA + sn * stageA + 16, Ap + 8);
            CP_ASYNC16(dstB + sn * stageB, Bp); CP_ASYNC16(dstB + sn * stageB + 16, Bp + 8);
        }
        CP_COMMIT();
        CP_WAIT1();
        __syncthreads();

        uint32_t baseA = sA0 + s * stageA;
        uint32_t baseB = sB0 + s * stageB;
#pragma unroll
        for (int kh = 0; kh < 2; kh++) {
            uint32_t af[4][4], bf[4][2];
#pragma unroll
            for (int mt = 0; mt < 4; mt++) ldm_x4(af[mt], baseA + a_off[mt] + kh * 32);
#pragma unroll
            for (int nt = 0; nt < 4; nt++) ldm_x2(bf[nt], baseB + b_off[nt] + kh * 32);
#pragma unroll
            for (int mt = 0; mt < 4; mt++)
#pragma unroll
                for (int nt = 0; nt < 4; nt++) mma_bf16(acc[mt][nt], af[mt], bf[nt]);
        }
        __syncthreads();
    }

    float* dst = (mat ? g_g2p[ks] : g_g1p[ks]) + (size_t)b * MAT;
    int grp = lane >> 2, qp = lane & 3;
#pragma unroll
    for (int mt = 0; mt < 4; mt++) {
        int row0 = ti * 128 + warp_m * 64 + mt * 16;
#pragma unroll
        for (int nt = 0; nt < 4; nt++) {
            int col0 = tj * 128 + warp_n * 32 + nt * 8 + qp * 2;
            float2 v0 = make_float2(acc[mt][nt][0], acc[mt][nt][1]);
            float2 v1 = make_float2(acc[mt][nt][2], acc[mt][nt][3]);
            *(float2*)(dst + (size_t)(row0 + grp) * CH + col0) = v0;
            *(float2*)(dst + (size_t)(row0 + grp + 8) * CH + col0) = v1;
        }
    }
}

// ---------------- reduce partials -> centered covariance (+frobenius partials) ----
__global__ void __launch_bounds__(256) cov_reduce_kernel() {
    int b = blockIdx.y;
    int idx = blockIdx.x * 256 + threadIdx.x;
    int i = idx >> 8, j = idx & 255;
    int si = (i <= j) ? i : j;
    int sj = (i <= j) ? j : i;
    float s = 0.f;
#pragma unroll
    for (int ks = 0; ks < KSG; ks++) {
        s += g_g1p[ks][(size_t)b * MAT + si * CH + sj];
        s += g_g2p[ks][(size_t)b * MAT + idx];
        s += g_g2p[ks][(size_t)b * MAT + j * CH + i];
    }
    float v = s * (1.f / MSP) - g_mu[b * CH + i] * g_mu[b * CH + j];
    g_cov[(size_t)b * MAT + idx] = v;
    float sq = blockReduceSum256(v * v);
    if (threadIdx.x == 0) g_fpart[b][blockIdx.x] = sq;
}

// ---------------- finalize frobenius norm ----------------
__global__ void __launch_bounds__(256) frob2_kernel() {
    int b = blockIdx.x;
    float s = blockReduceSum256(g_fpart[b][threadIdx.x]);
    if (threadIdx.x == 0) {
        float n = sqrtf(s);
        g_invN[b] = 1.f / n;
        g_rs[b] = rsqrtf(n);
    }
}

// ---------------- init: Y0 = cov/normA (hi/lo), Z0 = I (hi/lo) ----------------
__global__ void __launch_bounds__(256) init_kernel() {
    int b = blockIdx.y;
    int idx = blockIdx.x * 256 + threadIdx.x;
    size_t o = (size_t)b * MAT + idx;
    float v = g_cov[o] * g_invN[b];
    __nv_bfloat16 h = __float2bfloat16(v);
    g_Yh[0][o] = h;
    g_Yl[0][o] = __float2bfloat16(v - __bfloat162float(h));
    int i = idx >> 8, j = idx & 255;
    g_Zh[0][o] = __float2bfloat16((i == j) ? 1.f : 0.f);
    g_Zl[0][o] = __float2bfloat16(0.f);
}

// ---------------- NS matmul via HMMA: C = A.B (A,B symmetric, split bf16) ------
// 64x64 tile/CTA, 128 thr (4 warps, 2x2, 32x32 warp tiles), K = 3 terms x 256
__device__ __forceinline__ void ns_mm_body(
    const __nv_bfloat16* __restrict__ Ah, const __nv_bfloat16* __restrict__ Al,
    const __nv_bfloat16* __restrict__ Bh, const __nv_bfloat16* __restrict__ Bl,
    __nv_bfloat16* __restrict__ Ch, __nv_bfloat16* __restrict__ Cl,
    float* __restrict__ Cf, bool tEpi) {
    __shared__ __nv_bfloat16 sA[2][NS_STAGE];
    __shared__ __nv_bfloat16 sB[2][NS_STAGE];
    int bb = blockIdx.y;
    size_t boff = (size_t)bb * MAT;
    int ti = blockIdx.x >> 2, tj = blockIdx.x & 3;
    int tid = threadIdx.x, wid = tid >> 5, lane = tid & 31;
    int warp_m = wid & 1, warp_n = wid >> 1;

    const __nv_bfloat16* As[3] = {Ah + boff, Ah + boff, Al + boff};
    const __nv_bfloat16* Bs[3] = {Bh + boff, Bl + boff, Bh + boff};

    uint32_t sA0 = smem_u32(&sA[0][0]), sB0 = smem_u32(&sB[0][0]);
    const uint32_t stage = NS_STAGE * 2;  // bytes

    int lr = tid >> 1;        // 0..63 row
    int lsp = (tid & 1) * 4;  // starting 16B segment (4 segs each)
    uint32_t dA = sA0 + (uint32_t)(lr * NSTR + lsp * 8) * 2;
    uint32_t dB = sB0 + (uint32_t)(lr * NSTR + lsp * 8) * 2;

    uint32_t a_off[2], b_off[2];
#pragma unroll
    for (int mt = 0; mt < 2; mt++) {
        int row = warp_m * 32 + mt * 16 + (lane & 15);
        a_off[mt] = (uint32_t)(row * NSTR + (lane >> 4) * 8) * 2;
    }
#pragma unroll
    for (int np = 0; np < 2; np++) {  // n-tile pairs {0,1},{2,3}
        int row = warp_n * 32 + np * 16 + (lane >> 4) * 8 + (lane & 7);
        b_off[np] = (uint32_t)(row * NSTR + ((lane >> 3) & 1) * 8) * 2;
    }

    float acc[2][4][4];
#pragma unroll
    for (int i = 0; i < 2; i++)
#pragma unroll
        for (int j = 0; j < 4; j++)
#pragma unroll
            for (int k = 0; k < 4; k++) acc[i][j][k] = 0.f;

    {  // prologue: chunk 0
        const __nv_bfloat16* Ap = As[0] + (size_t)(ti * 64 + lr) * CH + lsp * 8;
        const __nv_bfloat16* Bp = Bs[0] + (size_t)(tj * 64 + lr) * CH + lsp * 8;
#pragma unroll
        for (int s4 = 0; s4 < 4; s4++) {
            CP_ASYNC16(dA + s4 * 16, Ap + s4 * 8);
            CP_ASYNC16(dB + s4 * 16, Bp + s4 * 8);
        }
        CP_COMMIT();
    }

    for (int c = 0; c < 12; c++) {  // 3 terms x 4 chunks of K=64
        int s = c & 1;
        if (c + 1 < 12) {
            int t1 = (c + 1) >> 2, kk1 = ((c + 1) & 3) * 64;
            int sn = (c + 1) & 1;
            const __nv_bfloat16* Ap = As[t1] + (size_t)(ti * 64 + lr) * CH + kk1 + lsp * 8;
            const __nv_bfloat16* Bp = Bs[t1] + (size_t)(tj * 64 + lr) * CH + kk1 + lsp * 8;
#pragma unroll
            for (int s4 = 0; s4 < 4; s4++) {
                CP_ASYNC16(dA + sn * stage + s4 * 16, Ap + s4 * 8);
                CP_ASYNC16(dB + sn * stage + s4 * 16, Bp + s4 * 8);
            }
        }
        CP_COMMIT();
        CP_WAIT1();
        __syncthreads();

        uint32_t bA = sA0 + s * stage, bB = sB0 + s * stage;
#pragma unroll
        for (int kh = 0; kh < 4; kh++) {
            uint32_t af[2][4], bfr[2][4];
#pragma unroll
            for (int mt = 0; mt < 2; mt++) ldm_x4(af[mt], bA + a_off[mt] + kh * 32);
#pragma unroll
            for (int np = 0; np < 2; np++) ldm_x4(bfr[np], bB + b_off[np] + kh * 32);
#pragma unroll
            for (int mt = 0; mt < 2; mt++)
#pragma unroll
                for (int nt = 0; nt < 4; nt++)
                    mma_bf16(acc[mt][nt], af[mt], &bfr[nt >> 1][(nt & 1) * 2]);
        }
        __syncthreads();
    }

    // epilogue: optional T-transform, split to hi/lo bf16, optional fp32
    int grp = lane >> 2, qp = lane & 3;
#pragma unroll
    for (int mt = 0; mt < 2; mt++)
#pragma unroll
        for (int half = 0; half < 2; half++) {
            int row = ti * 64 + warp_m * 32 + mt * 16 + grp + half * 8;
#pragma unroll
            for (int nt = 0; nt < 4; nt++) {
                int col = tj * 64 + warp_n * 32 + nt * 8 + qp * 2;
                float v0 = acc[mt][nt][half * 2];
                float v1 = acc[mt][nt][half * 2 + 1];
                if (tEpi) {
                    v0 = ((row == col) ? 1.5f : 0.f) - 0.5f * v0;
                    v1 = ((row == col + 1) ? 1.5f : 0.f) - 0.5f * v1;
                }
                __nv_bfloat16 h0 = __float2bfloat16(v0);
                __nv_bfloat16 h1 = __float2bfloat16(v1);
                __nv_bfloat162 hv, lv;
                hv.x = h0; hv.y = h1;
                lv.x = __float2bfloat16(v0 - __bfloat162float(h0));
                lv.y = __float2bfloat16(v1 - __bfloat162float(h1));
                size_t o = boff + (size_t)row * CH + col;
                *(__nv_bfloat162*)(Ch + o) = hv;
                *(__nv_bfloat162*)(Cl + o) = lv;
                if (Cf) *(float2*)(Cf + o) = make_float2(v0, v1);
            }
        }
}

// T = 1.5I - 0.5 * Z@Y   (A=Z, B=Y symmetric)
__global__ void __launch_bounds__(128) nsT_kernel(int cur) {
    ns_mm_body(g_Zh[cur], g_Zl[cur], g_Yh[cur], g_Yl[cur], g_Th, g_Tl, nullptr, true);
}
// z=0: Ynew = Y@T ; z=1: Znew = Z@T (= T@Z by commutation), also fp32 Z
__global__ void __launch_bounds__(128) nsYZ_kernel(int cur) {
    int z = blockIdx.z;
    const __nv_bfloat16* Ah = z ? g_Zh[cur] : g_Yh[cur];
    const __nv_bfloat16* Al = z ? g_Zl[cur] : g_Yl[cur];
    __nv_bfloat16* Ch = z ? g_Zh[cur ^ 1] : g_Yh[cur ^ 1];
    __nv_bfloat16* Cl = z ? g_Zl[cur ^ 1] : g_Yl[cur ^ 1];
    float* Cf = z ? g_Zf : nullptr;
    ns_mm_body(Ah, Al, g_Th, g_Tl, Ch, Cl, Cf, false);
}

// ---------------- y = rowmean(Z)/sqrt(normA) ----------------
__global__ void __launch_bounds__(256) rowmean_kernel() {
    int b = blockIdx.x, c = threadIdx.x;
    const float4* row = (const float4*)(g_Zf + ((size_t)b * CH + c) * CH);
    float s = 0.f;
#pragma unroll 8
    for (int d = 0; d < CH / 4; d++) {
        float4 v = row[d];
        s += v.x + v.y + v.z + v.w;
    }
    g_yv[b * CH + c] = s * (1.f / CH) * g_rs[b];
}

// ---------------- squeeze-excite MLP + sigmoid ----------------
__global__ void __launch_bounds__(256) se_kernel(const float* __restrict__ w1,
                                                 const float* __restrict__ b1,
                                                 const float* __restrict__ w2,
                                                 const float* __restrict__ b2) {
    int b = blockIdx.x;
    int tid = threadIdx.x;
    __shared__ float ys[CH];
    __shared__ float hs[32];
    ys[tid] = g_yv[b * CH + tid];
    __syncthreads();
    if (tid < 32) {
        float s = b1[tid];
        const float* w = w1 + tid * CH;
#pragma unroll 8
        for (int c = 0; c < CH; c++) s = fmaf(ys[c], w[c], s);
        hs[tid] = fmaxf(s, 0.f);
    }
    __syncthreads();
    float s = b2[tid];
    const float* w = w2 + tid * 32;
#pragma unroll
    for (int j = 0; j < 32; j++) s = fmaf(hs[j], w[j], s);
    g_gate[b * CH + tid] = 1.f / (1.f + expf(-s));
}

// ---------------- out = x * gate[b,c] ----------------
__global__ void __launch_bounds__(256) scale_kernel(const float* __restrict__ x,
                                                    float* __restrict__ out) {
    const float4* xi = (const float4*)x;
    float4* oo = (float4*)out;
    const size_t total = (size_t)BATCH * CH * MSP / 4;
    for (size_t i = (size_t)blockIdx.x * blockDim.x + threadIdx.x; i < total;
         i += (size_t)gridDim.x * blockDim.x) {
        float g = g_gate[i >> 12];
        float4 v = xi[i];
        v.x *= g; v.y *= g; v.z *= g; v.w *= g;
        oo[i] = v;
    }
}

// ---------------- launch ----------------
extern "C" void kernel_launch(void* const* d_in, const int* in_sizes, int n_in,
                              void* d_out, int out_size) {
    const float* x = (const float*)d_in[0];
    const float* w1 = (const float*)d_in[1];
    const float* b1 = (const float*)d_in[2];
    const float* w2 = (const float*)d_in[3];
    const float* b2 = (const float*)d_in[4];
    float* out = (float*)d_out;

    convert_kernel<<<BATCH * CH, 256>>>(x);
    gram_hmma_kernel<<<dim3(7, KSG, BATCH), 256>>>();
    cov_reduce_kernel<<<dim3(256, BATCH), 256>>>();
    frob2_kernel<<<BATCH, 256>>>();
    init_kernel<<<dim3(MAT / 256, BATCH), 256>>>();

    int cur = 0;
    for (int it = 0; it < 5; it++) {
        nsT_kernel<<<dim3(16, BATCH), 128>>>(cur);
        nsYZ_kernel<<<dim3(16, BATCH, 2), 128>>>(cur);
        cur ^= 1;
    }

    rowmean_kernel<<<BATCH, 256>>>();
    se_kernel<<<BATCH, 256>>>(w1, b1, w2, b2);
    scale_kernel<<<8192, 256>>>(x, out);
}